// round 6
// baseline (speedup 1.0000x reference)
#include <cuda_runtime.h>
#include <cuda_bf16.h>

// BilateralGridCP4D fused eval.
// Round-6: revert f32x2 (regressed), keep single setup-kernel + 1-memcpy
// constant plumbing, and go 2 points/thread for ILP (two independent
// dependency chains per thread; latency-bound kernel per R5 ncu).

#define RANK 5
#define THREADS 256

// layout: [0..59] fac0^T (idx = r*12 + j), [60..91] (w1[h][0..2],b1[h]) per h,
//         [92..99] w2, [100] b2
__constant__ float c_params[104];
__device__   float g_staging[104];

__global__ void setup_kernel(const float* __restrict__ fac0,
                             const float* __restrict__ w1,
                             const float* __restrict__ b1,
                             const float* __restrict__ w2,
                             const float* __restrict__ b2)
{
    int t = threadIdx.x;
    if (t < 60) {                        // fac0 transpose: [r][j] <- fac0[j][r]
        int r = t / 12, j = t % 12;
        g_staging[t] = fac0[j * RANK + r];
    } else if (t < 92) {                 // (w1 row, b1) packed per hidden unit
        int k = t - 60, h = k / 4, c = k % 4;
        g_staging[t] = (c < 3) ? w1[h * 3 + c] : b1[h];
    } else if (t < 100) {
        g_staging[t] = w2[t - 92];
    } else if (t == 100) {
        g_staging[100] = b2[0];
    }
}

// pt[i*RANK + r] = (f0, f1-f0); val = f0 + w*delta
__device__ __forceinline__ void interp_mul_pt(const float2* __restrict__ pt, int D,
                                              float pos, float coef[RANK], bool first)
{
    pos = fminf(fmaxf(pos, 0.0f), (float)(D - 1));
    int i0 = min((int)pos, D - 2);
    float w = pos - (float)i0;
    const float2* p = pt + i0 * RANK;
#pragma unroll
    for (int r = 0; r < RANK; r++) {
        float2 f = p[r];
        float val = fmaf(w, f.y, f.x);
        if (first) coef[r] = val;
        else       coef[r] *= val;
    }
}

// tanh(2a) = 1 - 2/(exp(4a)+1), via MUFU. Rel err ~1e-6.
__device__ __forceinline__ float fast_tanh2(float a)
{
    float e = __expf(4.0f * a);
    return 1.0f - __fdividef(2.0f, e + 1.0f);
}

__global__ __launch_bounds__(THREADS)
void bgrid_cp4d_kernel(const float2* __restrict__ xyz2,
                       const float2* __restrict__ rgb2,
                       const float* __restrict__ fac1,  // (5,8)
                       const float* __restrict__ fac2,  // (5,16)
                       const float* __restrict__ fac3,  // (5,16)
                       const float* __restrict__ fac4,  // (5,16)
                       float4* __restrict__ out4,       // N*3 float4
                       int nhalf)                        // N/2
{
    __shared__ float2 s_t1[7 * RANK];    // D=8
    __shared__ float2 s_t2[15 * RANK];   // D=16
    __shared__ float2 s_t3[15 * RANK];
    __shared__ float2 s_t4[15 * RANK];

    int tid = threadIdx.x;
    if (tid < 35) {
        int i = tid / RANK, r = tid % RANK;
        float a = fac1[r * 8 + i], b = fac1[r * 8 + i + 1];
        s_t1[tid] = make_float2(a, b - a);
    }
    if (tid < 75) {
        int i = tid / RANK, r = tid % RANK;
        float a = fac2[r * 16 + i], b = fac2[r * 16 + i + 1];
        s_t2[tid] = make_float2(a, b - a);
    } else if (tid < 150) {
        int k = tid - 75, i = k / RANK, r = k % RANK;
        float a = fac3[r * 16 + i], b = fac3[r * 16 + i + 1];
        s_t3[k] = make_float2(a, b - a);
    } else if (tid < 225) {
        int k = tid - 150, i = k / RANK, r = k % RANK;
        float a = fac4[r * 16 + i], b = fac4[r * 16 + i + 1];
        s_t4[k] = make_float2(a, b - a);
    }
    __syncthreads();

    int t = blockIdx.x * THREADS + tid;
    if (t >= nhalf) return;

    // 2 points/thread: 24 B of xyz and rgb each, as 3 aligned float2 loads
    float2 a0 = xyz2[3 * t + 0];   // x0 y0
    float2 a1 = xyz2[3 * t + 1];   // z0 x1
    float2 a2 = xyz2[3 * t + 2];   // y1 z1
    float2 c0 = rgb2[3 * t + 0];
    float2 c1 = rgb2[3 * t + 1];
    float2 c2 = rgb2[3 * t + 2];

    float px[2] = {a0.x, a1.y};
    float py[2] = {a0.y, a2.x};
    float pz[2] = {a1.x, a2.y};
    float cr[2] = {c0.x, c1.y};
    float cg[2] = {c0.y, c2.x};
    float cb[2] = {c1.x, c2.y};

    // ---- rgb -> gray MLP for both points (constant/uniform weight path) ----
    float gray[2];
#pragma unroll
    for (int p = 0; p < 2; p++) {
        float acc = c_params[100];
#pragma unroll
        for (int h = 0; h < 8; h++) {
            const float4 mw = *reinterpret_cast<const float4*>(&c_params[60 + 4 * h]);
            float hv = fmaf(mw.x, cr[p], fmaf(mw.y, cg[p], fmaf(mw.z, cb[p], mw.w)));
            hv = fmaxf(hv, 0.0f);
            acc = fmaf(c_params[92 + h], hv, acc);
        }
        gray[p] = fast_tanh2(acc);
    }

    // ---- CP products + 5->12 linear + store, per point ----
#pragma unroll
    for (int p = 0; p < 2; p++) {
        // pos = (v/BOUND + 1)*0.5*(D-1), BOUND=2 -> pos = v*0.25*(D-1)+0.5*(D-1)
        float coef[RANK];
        interp_mul_pt(s_t1, 8,  fmaf(px[p], 1.75f, 3.5f), coef, true);
        interp_mul_pt(s_t2, 16, fmaf(py[p], 3.75f, 7.5f), coef, false);
        interp_mul_pt(s_t3, 16, fmaf(pz[p], 3.75f, 7.5f), coef, false);
        interp_mul_pt(s_t4, 16, fmaf(gray[p], 7.5f, 7.5f), coef, false);

        float o[12];
#pragma unroll
        for (int j = 0; j < 12; j++)
            o[j] = coef[0] * c_params[0 * 12 + j];
#pragma unroll
        for (int r = 1; r < RANK; r++)
#pragma unroll
            for (int j = 0; j < 12; j++)
                o[j] = fmaf(coef[r], c_params[r * 12 + j], o[j]);

        int base = 6 * t + 3 * p;
        out4[base + 0] = make_float4(o[0], o[1], o[2],  o[3]);
        out4[base + 1] = make_float4(o[4], o[5], o[6],  o[7]);
        out4[base + 2] = make_float4(o[8], o[9], o[10], o[11]);
    }
}

extern "C" void kernel_launch(void* const* d_in, const int* in_sizes, int n_in,
                              void* d_out, int out_size)
{
    const float2* xyz2 = (const float2*)d_in[0];
    const float2* rgb2 = (const float2*)d_in[1];
    const float*  fac1 = (const float*)d_in[3];
    const float*  fac2 = (const float*)d_in[4];
    const float*  fac3 = (const float*)d_in[5];
    const float*  fac4 = (const float*)d_in[6];
    float4* out4 = (float4*)d_out;

    // Gather uniform params (one kernel node) then one memcpy into constant.
    setup_kernel<<<1, 128>>>((const float*)d_in[2], (const float*)d_in[7],
                             (const float*)d_in[8], (const float*)d_in[9],
                             (const float*)d_in[10]);
    void* staging_ptr = nullptr;
    cudaGetSymbolAddress(&staging_ptr, g_staging);
    cudaMemcpyToSymbolAsync(c_params, staging_ptr, 101 * sizeof(float), 0,
                            cudaMemcpyDeviceToDevice, 0);

    int npts  = in_sizes[0] / 3;   // N
    int nhalf = npts / 2;          // N = 2^22, divisible by 2
    int blocks = (nhalf + THREADS - 1) / THREADS;
    bgrid_cp4d_kernel<<<blocks, THREADS>>>(xyz2, rgb2, fac1, fac2, fac3, fac4,
                                           out4, nhalf);
}

// round 7
// speedup vs baseline: 1.0878x; 1.0878x over previous
#include <cuda_runtime.h>
#include <cuda_bf16.h>

// BilateralGridCP4D fused eval, 1 point/thread.
// Round-7: recombine R4's best kernel body (1pt/thread scalar, constant
// params, 32 regs, 87% occ -> 55.9us) with R5's best plumbing (setup kernel
// + single memcpyToSymbol, 5.6us overhead). Micro-trims: clamp folded into
// float min (no integer min), no lower clamp on gray axis.

#define RANK 5
#define THREADS 256

// layout: [0..59] fac0^T (idx = r*12 + j), [60..91] (w1[h][0..2],b1[h]) per h,
//         [92..99] w2, [100] b2
__constant__ float c_params[104];
__device__   float g_staging[104];

__global__ void setup_kernel(const float* __restrict__ fac0,
                             const float* __restrict__ w1,
                             const float* __restrict__ b1,
                             const float* __restrict__ w2,
                             const float* __restrict__ b2)
{
    int t = threadIdx.x;
    if (t < 60) {                        // fac0 transpose: [r][j] <- fac0[j][r]
        int r = t / 12, j = t % 12;
        g_staging[t] = fac0[j * RANK + r];
    } else if (t < 92) {                 // (w1 row, b1) packed per hidden unit
        int k = t - 60, h = k / 4, c = k % 4;
        g_staging[t] = (c < 3) ? w1[h * 3 + c] : b1[h];
    } else if (t < 100) {
        g_staging[t] = w2[t - 92];
    } else if (t == 100) {
        g_staging[100] = b2[0];
    }
}

// pt[i*RANK + r] = (f0, f1-f0); val = f0 + w*delta
// pos already clamped so that (int)pos <= D-2.
__device__ __forceinline__ void interp_mul_pt(const float2* __restrict__ pt,
                                              float pos, float coef[RANK], bool first)
{
    int i0 = (int)pos;
    float w = pos - (float)i0;
    const float2* p = pt + i0 * RANK;
#pragma unroll
    for (int r = 0; r < RANK; r++) {
        float2 f = p[r];
        float val = fmaf(w, f.y, f.x);
        if (first) coef[r] = val;
        else       coef[r] *= val;
    }
}

// tanh(2a) = 1 - 2/(exp(4a)+1), via MUFU. Rel err ~1e-6.
__device__ __forceinline__ float fast_tanh2(float a)
{
    float e = __expf(4.0f * a);
    return 1.0f - __fdividef(2.0f, e + 1.0f);
}

__global__ __launch_bounds__(THREADS)
void bgrid_cp4d_kernel(const float* __restrict__ xyz,
                       const float* __restrict__ rgb,
                       const float* __restrict__ fac1,  // (5,8)
                       const float* __restrict__ fac2,  // (5,16)
                       const float* __restrict__ fac3,  // (5,16)
                       const float* __restrict__ fac4,  // (5,16)
                       float4* __restrict__ out4,       // N*3 float4
                       int npts)
{
    __shared__ float2 s_t1[7 * RANK];    // D=8
    __shared__ float2 s_t2[15 * RANK];   // D=16
    __shared__ float2 s_t3[15 * RANK];
    __shared__ float2 s_t4[15 * RANK];

    int tid = threadIdx.x;
    if (tid < 35) {
        int i = tid / RANK, r = tid % RANK;
        float a = fac1[r * 8 + i], b = fac1[r * 8 + i + 1];
        s_t1[tid] = make_float2(a, b - a);
    }
    if (tid < 75) {
        int i = tid / RANK, r = tid % RANK;
        float a = fac2[r * 16 + i], b = fac2[r * 16 + i + 1];
        s_t2[tid] = make_float2(a, b - a);
    } else if (tid < 150) {
        int k = tid - 75, i = k / RANK, r = k % RANK;
        float a = fac3[r * 16 + i], b = fac3[r * 16 + i + 1];
        s_t3[k] = make_float2(a, b - a);
    } else if (tid < 225) {
        int k = tid - 150, i = k / RANK, r = k % RANK;
        float a = fac4[r * 16 + i], b = fac4[r * 16 + i + 1];
        s_t4[k] = make_float2(a, b - a);
    }
    __syncthreads();

    int i = blockIdx.x * THREADS + tid;
    if (i >= npts) return;

    float x  = xyz[3 * i + 0];
    float y  = xyz[3 * i + 1];
    float z  = xyz[3 * i + 2];
    float r0 = rgb[3 * i + 0];
    float g0 = rgb[3 * i + 1];
    float b0 = rgb[3 * i + 2];

    // ---- rgb -> gray MLP (uniform constant path, no L1tex) ----
    float acc = c_params[100];
#pragma unroll
    for (int h = 0; h < 8; h++) {
        const float4 mw = *reinterpret_cast<const float4*>(&c_params[60 + 4 * h]);
        float hv = fmaf(mw.x, r0, fmaf(mw.y, g0, fmaf(mw.z, b0, mw.w)));
        hv = fmaxf(hv, 0.0f);
        acc = fmaf(c_params[92 + h], hv, acc);
    }
    float gray = fast_tanh2(acc);

    // ---- CP factor products (pos = v*0.25*(D-1) + 0.5*(D-1), BOUND=2) ----
    // Clamp upper bound to just below D-1 so (int)pos <= D-2 with no int min.
    const float HI8  = 6.9999995f;    // largest useful pos for D=8
    const float HI16 = 14.999999f;    // for D=16
    float p1 = fminf(fmaxf(fmaf(x, 1.75f, 3.5f), 0.0f), HI8);
    float p2 = fminf(fmaxf(fmaf(y, 3.75f, 7.5f), 0.0f), HI16);
    float p3 = fminf(fmaxf(fmaf(z, 3.75f, 7.5f), 0.0f), HI16);
    float p4 = fminf(fmaf(gray, 7.5f, 7.5f), HI16);   // gray >= -1 -> pos >= 0

    float coef[RANK];
    interp_mul_pt(s_t1, p1, coef, true);
    interp_mul_pt(s_t2, p2, coef, false);
    interp_mul_pt(s_t3, p3, coef, false);
    interp_mul_pt(s_t4, p4, coef, false);

    // ---- 5 -> 12 linear, fac0^T from constant (r-major, LDCU-pair friendly) ----
    float o[12];
#pragma unroll
    for (int j = 0; j < 12; j++)
        o[j] = coef[0] * c_params[j];
#pragma unroll
    for (int r = 1; r < RANK; r++)
#pragma unroll
        for (int j = 0; j < 12; j++)
            o[j] = fmaf(coef[r], c_params[r * 12 + j], o[j]);

    int base = 3 * i;
    out4[base + 0] = make_float4(o[0], o[1], o[2],  o[3]);
    out4[base + 1] = make_float4(o[4], o[5], o[6],  o[7]);
    out4[base + 2] = make_float4(o[8], o[9], o[10], o[11]);
}

extern "C" void kernel_launch(void* const* d_in, const int* in_sizes, int n_in,
                              void* d_out, int out_size)
{
    const float* xyz  = (const float*)d_in[0];
    const float* rgb  = (const float*)d_in[1];
    const float* fac1 = (const float*)d_in[3];
    const float* fac2 = (const float*)d_in[4];
    const float* fac3 = (const float*)d_in[5];
    const float* fac4 = (const float*)d_in[6];
    float4* out4 = (float4*)d_out;

    // Gather uniform params (one kernel node) then one memcpy into constant.
    setup_kernel<<<1, 128>>>((const float*)d_in[2], (const float*)d_in[7],
                             (const float*)d_in[8], (const float*)d_in[9],
                             (const float*)d_in[10]);
    void* staging_ptr = nullptr;
    cudaGetSymbolAddress(&staging_ptr, g_staging);
    cudaMemcpyToSymbolAsync(c_params, staging_ptr, 101 * sizeof(float), 0,
                            cudaMemcpyDeviceToDevice, 0);

    int npts = in_sizes[0] / 3;
    int blocks = (npts + THREADS - 1) / THREADS;
    bgrid_cp4d_kernel<<<blocks, THREADS>>>(xyz, rgb, fac1, fac2, fac3, fac4,
                                           out4, npts);
}

// round 8
// speedup vs baseline: 1.1000x; 1.0112x over previous
#include <cuda_runtime.h>
#include <cuda_bf16.h>

// BilateralGridCP4D fused eval, 1 point/thread.
// Round-8: R4's proven kernel body (ALL constant reads scalar -> LDCU uniform
// path; float4-from-constant becomes half-rate LDC.128 and regressed in R5/R7)
// + R5's proven plumbing (setup kernel + single memcpyToSymbol).
// Kept trims: (f0, delta) interp tables, float-folded index clamps.

#define RANK 5
#define THREADS 256

// layout: [0..59] fac0 native (12,5) row-major, [60..83] w1 (8,3),
//         [84..91] b1, [92..99] w2, [100] b2
__constant__ float c_params[104];
__device__   float g_staging[104];

__global__ void setup_kernel(const float* __restrict__ fac0,
                             const float* __restrict__ w1,
                             const float* __restrict__ b1,
                             const float* __restrict__ w2,
                             const float* __restrict__ b2)
{
    int t = threadIdx.x;
    if (t < 60)        g_staging[t] = fac0[t];
    else if (t < 84)   g_staging[t] = w1[t - 60];
    else if (t < 92)   g_staging[t] = b1[t - 84];
    else if (t < 100)  g_staging[t] = w2[t - 92];
    else if (t == 100) g_staging[100] = b2[0];
}

// pt[i*RANK + r] = (f0, f1-f0); val = f0 + w*delta
// pos pre-clamped so (int)pos <= D-2.
__device__ __forceinline__ void interp_mul_pt(const float2* __restrict__ pt,
                                              float pos, float coef[RANK], bool first)
{
    int i0 = (int)pos;
    float w = pos - (float)i0;
    const float2* p = pt + i0 * RANK;
#pragma unroll
    for (int r = 0; r < RANK; r++) {
        float2 f = p[r];
        float val = fmaf(w, f.y, f.x);
        if (first) coef[r] = val;
        else       coef[r] *= val;
    }
}

// tanh(2a) = 1 - 2/(exp(4a)+1), via MUFU. Rel err ~1e-6.
__device__ __forceinline__ float fast_tanh2(float a)
{
    float e = __expf(4.0f * a);
    return 1.0f - __fdividef(2.0f, e + 1.0f);
}

__global__ __launch_bounds__(THREADS)
void bgrid_cp4d_kernel(const float* __restrict__ xyz,
                       const float* __restrict__ rgb,
                       const float* __restrict__ fac1,  // (5,8)
                       const float* __restrict__ fac2,  // (5,16)
                       const float* __restrict__ fac3,  // (5,16)
                       const float* __restrict__ fac4,  // (5,16)
                       float4* __restrict__ out4,       // N*3 float4
                       int npts)
{
    __shared__ float2 s_t1[7 * RANK];    // D=8
    __shared__ float2 s_t2[15 * RANK];   // D=16
    __shared__ float2 s_t3[15 * RANK];
    __shared__ float2 s_t4[15 * RANK];

    int tid = threadIdx.x;
    if (tid < 35) {
        int i = tid / RANK, r = tid % RANK;
        float a = fac1[r * 8 + i], b = fac1[r * 8 + i + 1];
        s_t1[tid] = make_float2(a, b - a);
    }
    if (tid < 75) {
        int i = tid / RANK, r = tid % RANK;
        float a = fac2[r * 16 + i], b = fac2[r * 16 + i + 1];
        s_t2[tid] = make_float2(a, b - a);
    } else if (tid < 150) {
        int k = tid - 75, i = k / RANK, r = k % RANK;
        float a = fac3[r * 16 + i], b = fac3[r * 16 + i + 1];
        s_t3[k] = make_float2(a, b - a);
    } else if (tid < 225) {
        int k = tid - 150, i = k / RANK, r = k % RANK;
        float a = fac4[r * 16 + i], b = fac4[r * 16 + i + 1];
        s_t4[k] = make_float2(a, b - a);
    }
    __syncthreads();

    int i = blockIdx.x * THREADS + tid;
    if (i >= npts) return;

    float x  = xyz[3 * i + 0];
    float y  = xyz[3 * i + 1];
    float z  = xyz[3 * i + 2];
    float r0 = rgb[3 * i + 0];
    float g0 = rgb[3 * i + 1];
    float b0 = rgb[3 * i + 2];

    // ---- rgb -> gray MLP: scalar constant reads -> LDCU uniform path ----
    float acc = c_params[100];
#pragma unroll
    for (int h = 0; h < 8; h++) {
        float hv = fmaf(c_params[60 + h * 3 + 0], r0,
                   fmaf(c_params[60 + h * 3 + 1], g0,
                   fmaf(c_params[60 + h * 3 + 2], b0, c_params[84 + h])));
        hv = fmaxf(hv, 0.0f);
        acc = fmaf(c_params[92 + h], hv, acc);
    }
    float gray = fast_tanh2(acc);

    // ---- CP factor products (pos = v*0.25*(D-1) + 0.5*(D-1), BOUND=2) ----
    const float HI8  = 6.9999995f;
    const float HI16 = 14.999999f;
    float p1 = fminf(fmaxf(fmaf(x, 1.75f, 3.5f), 0.0f), HI8);
    float p2 = fminf(fmaxf(fmaf(y, 3.75f, 7.5f), 0.0f), HI16);
    float p3 = fminf(fmaxf(fmaf(z, 3.75f, 7.5f), 0.0f), HI16);
    float p4 = fminf(fmaf(gray, 7.5f, 7.5f), HI16);    // gray >= -1 -> pos >= 0

    float coef[RANK];
    interp_mul_pt(s_t1, p1, coef, true);
    interp_mul_pt(s_t2, p2, coef, false);
    interp_mul_pt(s_t3, p3, coef, false);
    interp_mul_pt(s_t4, p4, coef, false);

    // ---- 5 -> 12 linear, fac0 native (12,5), scalar LDCU reads ----
    float4 o[3];
#pragma unroll
    for (int q = 0; q < 3; q++) {
        o[q].x = coef[0] * c_params[(4 * q + 0) * RANK];
        o[q].y = coef[0] * c_params[(4 * q + 1) * RANK];
        o[q].z = coef[0] * c_params[(4 * q + 2) * RANK];
        o[q].w = coef[0] * c_params[(4 * q + 3) * RANK];
    }
#pragma unroll
    for (int r = 1; r < RANK; r++) {
#pragma unroll
        for (int q = 0; q < 3; q++) {
            o[q].x = fmaf(coef[r], c_params[(4 * q + 0) * RANK + r], o[q].x);
            o[q].y = fmaf(coef[r], c_params[(4 * q + 1) * RANK + r], o[q].y);
            o[q].z = fmaf(coef[r], c_params[(4 * q + 2) * RANK + r], o[q].z);
            o[q].w = fmaf(coef[r], c_params[(4 * q + 3) * RANK + r], o[q].w);
        }
    }

    int base = 3 * i;
    out4[base + 0] = o[0];
    out4[base + 1] = o[1];
    out4[base + 2] = o[2];
}

extern "C" void kernel_launch(void* const* d_in, const int* in_sizes, int n_in,
                              void* d_out, int out_size)
{
    const float* xyz  = (const float*)d_in[0];
    const float* rgb  = (const float*)d_in[1];
    const float* fac1 = (const float*)d_in[3];
    const float* fac2 = (const float*)d_in[4];
    const float* fac3 = (const float*)d_in[5];
    const float* fac4 = (const float*)d_in[6];
    float4* out4 = (float4*)d_out;

    // Gather uniform params (one kernel node) then one memcpy into constant.
    setup_kernel<<<1, 128>>>((const float*)d_in[2], (const float*)d_in[7],
                             (const float*)d_in[8], (const float*)d_in[9],
                             (const float*)d_in[10]);
    void* staging_ptr = nullptr;
    cudaGetSymbolAddress(&staging_ptr, g_staging);
    cudaMemcpyToSymbolAsync(c_params, staging_ptr, 101 * sizeof(float), 0,
                            cudaMemcpyDeviceToDevice, 0);

    int npts = in_sizes[0] / 3;
    int blocks = (npts + THREADS - 1) / THREADS;
    bgrid_cp4d_kernel<<<blocks, THREADS>>>(xyz, rgb, fac1, fac2, fac3, fac4,
                                           out4, npts);
}